// round 1
// baseline (speedup 1.0000x reference)
#include <cuda_runtime.h>
#include <math.h>

// ============================================================================
// DBTransformerLayer: hetero-graph transformer, 2 relations.
//
// Decomposition:
//  - Per-node precompute: qkv_dst[n] = x_dst[n] @ Wi^T + bi           [4,384]
//                         kv_src[n]  = x_src[n] @ Weff^T + beff       [4,256]
//        where Weff = Wi[128:384] @ bw  (b_proj folded into kv-proj)
//  - Per-edge: attention (4 q-tokens vs 8 kv-tokens), out_proj, LN1, FF, LN2,
//              scatter atomicAdd into output. Only first 4 tokens needed.
//  - counts + divide for scatter-mean.
// ============================================================================

#define MAX_N 20000
#define T4 4

// ------------------------------- scratch -----------------------------------
__device__ float g_qkv_dst0[(size_t)MAX_N * 4 * 384];
__device__ float g_qkv_dst1[(size_t)MAX_N * 4 * 384];
__device__ float g_kv_src0[(size_t)MAX_N * 4 * 256];
__device__ float g_kv_src1[(size_t)MAX_N * 4 * 256];
__device__ float g_weff[2 * 256 * 128];
__device__ float g_beff[2 * 256];
__device__ int   g_cnt[2 * MAX_N];

// ------------------------------- zero --------------------------------------
__global__ void zero_kernel(float* out, int n, int* cnt, int nc) {
    int stride = gridDim.x * blockDim.x;
    for (int i = blockIdx.x * blockDim.x + threadIdx.x; i < n; i += stride) out[i] = 0.f;
    for (int i = blockIdx.x * blockDim.x + threadIdx.x; i < nc; i += stride) cnt[i] = 0;
}

// ------------------------------- counts ------------------------------------
__global__ void count_kernel(const int* __restrict__ eAB, const int* __restrict__ eBA,
                             int E0, int E1, int* cnt, int NB) {
    int stride = gridDim.x * blockDim.x;
    int total = E0 + E1;
    for (int i = blockIdx.x * blockDim.x + threadIdx.x; i < total; i += stride) {
        if (i < E0) atomicAdd(&cnt[eAB[E0 + i]], 1);            // rel0 dst = B node
        else        atomicAdd(&cnt[NB + eBA[E1 + (i - E0)]], 1); // rel1 dst = A node
    }
}

// ------------------------ Weff = Wi[128:384] @ bw ---------------------------
__global__ void prep_weff(const float* __restrict__ wi, const float* __restrict__ bi,
                          const float* __restrict__ bw, const float* __restrict__ bb,
                          float* __restrict__ weff, float* __restrict__ beff) {
    // grid (256, 2), 128 threads
    int n = blockIdx.x;            // output row (kv row 128+n of wi)
    int r = blockIdx.y;
    int k = threadIdx.x;
    const float* wrow = wi + ((size_t)r * 384 + 128 + n) * 128;
    const float* bwr  = bw + (size_t)r * 16384;
    float acc = 0.f;
    for (int m = 0; m < 128; ++m) acc += wrow[m] * bwr[m * 128 + k];
    weff[((size_t)r * 256 + n) * 128 + k] = acc;

    __shared__ float red[128];
    red[k] = wrow[k] * bb[r * 128 + k];
    __syncthreads();
    for (int s = 64; s; s >>= 1) { if (k < s) red[k] += red[k + s]; __syncthreads(); }
    if (k == 0) beff[r * 256 + n] = bi[(size_t)r * 384 + 128 + n] + red[0];
}

// ------------------------ GEMM: C[M,Nout] = A[M,128] @ W[Nout,128]^T + b ----
#define GEMM_SMEM (2 * 128 * 68 * 4)
__global__ __launch_bounds__(256)
void gemm_k128(const float* __restrict__ A, const float* __restrict__ W,
               const float* __restrict__ bias, float* __restrict__ C,
               int M, int Nout) {
    extern __shared__ float gsm[];
    float* As = gsm;                // As[k][row], pad 68
    float* Ws = gsm + 128 * 68;     // Ws[k][col], pad 68
    int bm = blockIdx.x * 64, bn = blockIdx.y * 64;
    int tid = threadIdx.x;

    for (int i = tid; i < 8192; i += 256) {
        int row = i >> 7, k = i & 127;
        int gr = bm + row;
        As[k * 68 + row] = (gr < M) ? A[(size_t)gr * 128 + k] : 0.f;
    }
    for (int i = tid; i < 8192; i += 256) {
        int row = i >> 7, k = i & 127;
        Ws[k * 68 + row] = W[(size_t)(bn + row) * 128 + k];
    }
    __syncthreads();

    int ty = tid >> 4, tx = tid & 15;
    float acc[4][4];
    #pragma unroll
    for (int i = 0; i < 4; ++i)
        #pragma unroll
        for (int j = 0; j < 4; ++j) acc[i][j] = 0.f;

    #pragma unroll 4
    for (int k = 0; k < 128; ++k) {
        float4 a = *(const float4*)&As[k * 68 + ty * 4];
        float4 w = *(const float4*)&Ws[k * 68 + tx * 4];
        acc[0][0] += a.x * w.x; acc[0][1] += a.x * w.y; acc[0][2] += a.x * w.z; acc[0][3] += a.x * w.w;
        acc[1][0] += a.y * w.x; acc[1][1] += a.y * w.y; acc[1][2] += a.y * w.z; acc[1][3] += a.y * w.w;
        acc[2][0] += a.z * w.x; acc[2][1] += a.z * w.y; acc[2][2] += a.z * w.z; acc[2][3] += a.z * w.w;
        acc[3][0] += a.w * w.x; acc[3][1] += a.w * w.y; acc[3][2] += a.w * w.z; acc[3][3] += a.w * w.w;
    }

    float b0 = bias[bn + tx * 4 + 0];
    float b1 = bias[bn + tx * 4 + 1];
    float b2 = bias[bn + tx * 4 + 2];
    float b3 = bias[bn + tx * 4 + 3];
    #pragma unroll
    for (int i = 0; i < 4; ++i) {
        int gr = bm + ty * 4 + i;
        if (gr < M) {
            float4 o;
            o.x = acc[i][0] + b0; o.y = acc[i][1] + b1;
            o.z = acc[i][2] + b2; o.w = acc[i][3] + b3;
            *(float4*)&C[(size_t)gr * Nout + bn + tx * 4] = o;
        }
    }
}

// ------------------------------- edge kernel --------------------------------
// smem float offsets
#define S_WO   0                         // 128x129
#define S_L1   16512                     // 64x129
#define S_L2   24768                     // 128x65
#define S_BO   33088
#define S_L1B  33216
#define S_L2B  33280
#define S_N1W  33408
#define S_N1B  33536
#define S_N2W  33664
#define S_N2B  33792
#define S_QD   33920                     // 4x384
#define S_KVJ  35456                     // 4x256
#define S_XI   36480                     // 4x128
#define S_SC   36992                     // 4x8x8
#define S_O    37248                     // 4x128
#define S_U    37760                     // 4x128
#define S_XLN  38272                     // 4x128
#define S_H1   38784                     // 4x64
#define S_ST   39040                     // 4x2
#define S_TOTAL 39048
#define EDGE_SMEM (S_TOTAL * 4)

__global__ __launch_bounds__(256, 1)
void edge_kernel(const int* __restrict__ edge, int E,
                 const float* __restrict__ qkvd,   // [Ndst,4,384]
                 const float* __restrict__ kvs,    // [Nsrc,4,256]
                 const float* __restrict__ xdst,   // [Ndst,4,128]
                 const float* __restrict__ wo, const float* __restrict__ bo,
                 const float* __restrict__ l1w, const float* __restrict__ l1b,
                 const float* __restrict__ l2w, const float* __restrict__ l2b,
                 const float* __restrict__ n1w, const float* __restrict__ n1b,
                 const float* __restrict__ n2w, const float* __restrict__ n2b,
                 float* __restrict__ out)
{
    extern __shared__ float sm[];
    const int tid = threadIdx.x;

    // ---- one-time: weights into padded smem (conflict-free reads) ----
    for (int i = tid; i < 128 * 128; i += 256) sm[S_WO + (i >> 7) * 129 + (i & 127)] = wo[i];
    for (int i = tid; i < 64 * 128;  i += 256) sm[S_L1 + (i >> 7) * 129 + (i & 127)] = l1w[i];
    for (int i = tid; i < 128 * 64;  i += 256) sm[S_L2 + (i >> 6) * 65 + (i & 63)]  = l2w[i];
    if (tid < 128) {
        sm[S_BO + tid] = bo[tid];   sm[S_L2B + tid] = l2b[tid];
        sm[S_N1W + tid] = n1w[tid]; sm[S_N1B + tid] = n1b[tid];
        sm[S_N2W + tid] = n2w[tid]; sm[S_N2B + tid] = n2b[tid];
    }
    if (tid < 64) sm[S_L1B + tid] = l1b[tid];

    int chunk = (E + gridDim.x - 1) / gridDim.x;
    int e0 = blockIdx.x * chunk;
    int e1 = min(E, e0 + chunk);
    if (e0 >= e1) return;

    // ---- register pipeline for per-edge gathers ----
    float4 r0, r1, r2, r3;
    int rdst;
    {
        int s = edge[e0]; rdst = edge[E + e0];
        const float4* pq = (const float4*)(qkvd + (size_t)rdst * 1536);
        const float4* pk = (const float4*)(kvs + (size_t)s * 1024);
        const float4* px = (const float4*)(xdst + (size_t)rdst * 512);
        r0 = pq[tid];
        if (tid < 128) r1 = pq[256 + tid];
        r2 = pk[tid];
        if (tid < 128) r3 = px[tid];
    }

    const int d = tid & 127;
    const int th = tid >> 7;

    for (int e = e0; e < e1; ++e) {
        __syncthreads();                        // prev compute done with smem
        *(float4*)&sm[S_QD + tid * 4] = r0;
        if (tid < 128) *(float4*)&sm[S_QD + 1024 + tid * 4] = r1;
        *(float4*)&sm[S_KVJ + tid * 4] = r2;
        if (tid < 128) *(float4*)&sm[S_XI + tid * 4] = r3;
        const int dst = rdst;
        __syncthreads();

        if (e + 1 < e1) {                       // prefetch next edge (overlaps compute)
            int s = edge[e + 1]; rdst = edge[E + e + 1];
            const float4* pq = (const float4*)(qkvd + (size_t)rdst * 1536);
            const float4* pk = (const float4*)(kvs + (size_t)s * 1024);
            const float4* px = (const float4*)(xdst + (size_t)rdst * 512);
            r0 = pq[tid];
            if (tid < 128) r1 = pq[256 + tid];
            r2 = pk[tid];
            if (tid < 128) r3 = px[tid];
        }

        // ---- 1) attention scores (q tokens 0..3, kv tokens 0..7) ----
        {
            int t = tid >> 6, s = (tid >> 3) & 7, h = tid & 7;
            const float* qp = &sm[S_QD + t * 384 + h * 16];
            const float* kp = (s < 4) ? &sm[S_QD + s * 384 + 128 + h * 16]
                                      : &sm[S_KVJ + (s - 4) * 256 + h * 16];
            float acc = 0.f;
            #pragma unroll
            for (int j = 0; j < 16; ++j) acc += qp[j] * kp[j];
            sm[S_SC + tid] = acc * 0.25f;       // t*64 + s*8 + h
        }
        __syncthreads();
        // ---- 2) softmax over the 8 kv tokens ----
        if (tid < 32) {
            int t = tid >> 3, h = tid & 7;
            float v[8]; float mx = -1e30f;
            #pragma unroll
            for (int s = 0; s < 8; ++s) { v[s] = sm[S_SC + t * 64 + s * 8 + h]; mx = fmaxf(mx, v[s]); }
            float sum = 0.f;
            #pragma unroll
            for (int s = 0; s < 8; ++s) { v[s] = expf(v[s] - mx); sum += v[s]; }
            float inv = 1.f / sum;
            #pragma unroll
            for (int s = 0; s < 8; ++s) sm[S_SC + t * 64 + s * 8 + h] = v[s] * inv;
        }
        __syncthreads();
        // ---- 3) o = p @ v ----
        {
            int h = d >> 4;
            #pragma unroll
            for (int tt = 0; tt < 2; ++tt) {
                int t = th + tt * 2;
                float acc = 0.f;
                #pragma unroll
                for (int s = 0; s < 8; ++s) {
                    float p = sm[S_SC + t * 64 + s * 8 + h];
                    float v = (s < 4) ? sm[S_QD + s * 384 + 256 + d]
                                      : sm[S_KVJ + (s - 4) * 256 + 128 + d];
                    acc += p * v;
                }
                sm[S_O + t * 128 + d] = acc;
            }
        }
        __syncthreads();
        // ---- 4) out_proj + residual -> u ----
        {
            #pragma unroll
            for (int tt = 0; tt < 2; ++tt) {
                int t = th + tt * 2;
                float acc = sm[S_BO + d];
                const float* op = &sm[S_O + t * 128];
                const float* wp = &sm[S_WO + d * 129];
                #pragma unroll 8
                for (int k = 0; k < 128; ++k) acc += op[k] * wp[k];
                sm[S_U + t * 128 + d] = sm[S_XI + t * 128 + d] + acc;
            }
        }
        __syncthreads();
        // ---- 5) LN1 ----
        {
            int w = tid >> 5, lane = tid & 31;
            if (w < 4) {
                float s1 = 0.f, s2 = 0.f;
                #pragma unroll
                for (int j = 0; j < 4; ++j) { float v = sm[S_U + w * 128 + lane + j * 32]; s1 += v; s2 += v * v; }
                #pragma unroll
                for (int o = 16; o; o >>= 1) { s1 += __shfl_down_sync(0xffffffffu, s1, o); s2 += __shfl_down_sync(0xffffffffu, s2, o); }
                if (lane == 0) {
                    float m = s1 * (1.f / 128.f);
                    float var = s2 * (1.f / 128.f) - m * m;
                    sm[S_ST + w * 2] = m; sm[S_ST + w * 2 + 1] = rsqrtf(var + 1e-5f);
                }
            }
        }
        __syncthreads();
        {
            #pragma unroll
            for (int tt = 0; tt < 2; ++tt) {
                int t = th + tt * 2;
                float m = sm[S_ST + t * 2], rs = sm[S_ST + t * 2 + 1];
                sm[S_XLN + t * 128 + d] = (sm[S_U + t * 128 + d] - m) * rs * sm[S_N1W + d] + sm[S_N1B + d];
            }
        }
        __syncthreads();
        // ---- 6) lin1 + relu ----
        {
            int f = tid & 63, t = tid >> 6;
            float acc = sm[S_L1B + f];
            const float* xp = &sm[S_XLN + t * 128];
            const float* wp = &sm[S_L1 + f * 129];
            #pragma unroll 8
            for (int k = 0; k < 128; ++k) acc += xp[k] * wp[k];
            sm[S_H1 + t * 64 + f] = fmaxf(acc, 0.f);
        }
        __syncthreads();
        // ---- 7) lin2 + residual -> u2 ----
        {
            #pragma unroll
            for (int tt = 0; tt < 2; ++tt) {
                int t = th + tt * 2;
                float acc = sm[S_L2B + d];
                const float* hp = &sm[S_H1 + t * 64];
                const float* wp = &sm[S_L2 + d * 65];
                #pragma unroll 8
                for (int k = 0; k < 64; ++k) acc += hp[k] * wp[k];
                sm[S_U + t * 128 + d] = sm[S_XLN + t * 128 + d] + acc;
            }
        }
        __syncthreads();
        // ---- 8) LN2 stats ----
        {
            int w = tid >> 5, lane = tid & 31;
            if (w < 4) {
                float s1 = 0.f, s2 = 0.f;
                #pragma unroll
                for (int j = 0; j < 4; ++j) { float v = sm[S_U + w * 128 + lane + j * 32]; s1 += v; s2 += v * v; }
                #pragma unroll
                for (int o = 16; o; o >>= 1) { s1 += __shfl_down_sync(0xffffffffu, s1, o); s2 += __shfl_down_sync(0xffffffffu, s2, o); }
                if (lane == 0) {
                    float m = s1 * (1.f / 128.f);
                    float var = s2 * (1.f / 128.f) - m * m;
                    sm[S_ST + w * 2] = m; sm[S_ST + w * 2 + 1] = rsqrtf(var + 1e-5f);
                }
            }
        }
        __syncthreads();
        // ---- 9) normalize + scatter-add ----
        {
            float* ob = out + (size_t)dst * 512;
            #pragma unroll
            for (int tt = 0; tt < 2; ++tt) {
                int t = th + tt * 2;
                float m = sm[S_ST + t * 2], rs = sm[S_ST + t * 2 + 1];
                float val = (sm[S_U + t * 128 + d] - m) * rs * sm[S_N2W + d] + sm[S_N2B + d];
                atomicAdd(&ob[t * 128 + d], val);
            }
        }
    }
}

// ------------------------------- finalize -----------------------------------
__global__ void fin_kernel(float* out, const int* cnt, int NA, int NB) {
    int stride = gridDim.x * blockDim.x;
    int nA = NA * 512;
    int total = (NA + NB) * 512;
    for (int i = blockIdx.x * blockDim.x + threadIdx.x; i < total; i += stride) {
        int c;
        if (i < nA) c = cnt[NB + (i >> 9)];            // out_A region: rel1 counts
        else        c = cnt[(i - nA) >> 9];            // out_B region: rel0 counts
        if (c < 1) c = 1;
        out[i] = out[i] / (float)c;
    }
}

// ------------------------------- launch --------------------------------------
extern "C" void kernel_launch(void* const* d_in, const int* in_sizes, int n_in,
                              void* d_out, int out_size)
{
    const float* x_A = (const float*)d_in[0];
    const float* x_B = (const float*)d_in[1];
    const int*   eAB = (const int*)d_in[2];
    const int*   eBA = (const int*)d_in[3];
    const float* bw  = (const float*)d_in[4];
    const float* bb  = (const float*)d_in[5];
    const float* wi  = (const float*)d_in[6];
    const float* bi  = (const float*)d_in[7];
    const float* wo  = (const float*)d_in[8];
    const float* bo  = (const float*)d_in[9];
    const float* l1w = (const float*)d_in[10];
    const float* l1b = (const float*)d_in[11];
    const float* l2w = (const float*)d_in[12];
    const float* l2b = (const float*)d_in[13];
    const float* n1w = (const float*)d_in[14];
    const float* n1b = (const float*)d_in[15];
    const float* n2w = (const float*)d_in[16];
    const float* n2b = (const float*)d_in[17];
    float* out = (float*)d_out;

    int NA = in_sizes[0] / 512;
    int NB = in_sizes[1] / 512;
    int E0 = in_sizes[2] / 2;
    int E1 = in_sizes[3] / 2;

    float *qd0, *qd1, *kv0, *kv1, *weff, *beff;
    int* cnt;
    cudaGetSymbolAddress((void**)&qd0, g_qkv_dst0);
    cudaGetSymbolAddress((void**)&qd1, g_qkv_dst1);
    cudaGetSymbolAddress((void**)&kv0, g_kv_src0);
    cudaGetSymbolAddress((void**)&kv1, g_kv_src1);
    cudaGetSymbolAddress((void**)&weff, g_weff);
    cudaGetSymbolAddress((void**)&beff, g_beff);
    cudaGetSymbolAddress((void**)&cnt, g_cnt);

    cudaFuncSetAttribute(edge_kernel, cudaFuncAttributeMaxDynamicSharedMemorySize, EDGE_SMEM);
    cudaFuncSetAttribute(gemm_k128,   cudaFuncAttributeMaxDynamicSharedMemorySize, GEMM_SMEM);

    zero_kernel<<<512, 256>>>(out, (NA + NB) * 512, cnt, NA + NB);
    prep_weff<<<dim3(256, 2), 128>>>(wi, bi, bw, bb, weff, beff);
    count_kernel<<<256, 256>>>(eAB, eBA, E0, E1, cnt, NB);

    // node precompute GEMMs
    gemm_k128<<<dim3((NB * 4 + 63) / 64, 6), 256, GEMM_SMEM>>>(x_B, wi,               bi,        qd0, NB * 4, 384);
    gemm_k128<<<dim3((NA * 4 + 63) / 64, 4), 256, GEMM_SMEM>>>(x_A, weff,             beff,      kv0, NA * 4, 256);
    gemm_k128<<<dim3((NA * 4 + 63) / 64, 6), 256, GEMM_SMEM>>>(x_A, wi + 384 * 128,   bi + 384,  qd1, NA * 4, 384);
    gemm_k128<<<dim3((NB * 4 + 63) / 64, 4), 256, GEMM_SMEM>>>(x_B, weff + 256 * 128, beff + 256, kv1, NB * 4, 256);

    // relation 0: A->B updates B  (output region after out_A)
    edge_kernel<<<148, 256, EDGE_SMEM>>>(eAB, E0, qd0, kv0, x_B,
        wo, bo, l1w, l1b, l2w, l2b, n1w, n1b, n2w, n2b,
        out + (size_t)NA * 512);
    // relation 1: B->A updates A  (output region at start)
    edge_kernel<<<148, 256, EDGE_SMEM>>>(eBA, E1, qd1, kv1, x_A,
        wo + 16384, bo + 128, l1w + 8192, l1b + 64, l2w + 8192, l2b + 128,
        n1w + 128, n1b + 128, n2w + 128, n2b + 128,
        out);

    fin_kernel<<<512, 256>>>(out, cnt, NA, NB);
}

// round 2
// speedup vs baseline: 2.2085x; 2.2085x over previous
#include <cuda_runtime.h>
#include <math.h>

// ============================================================================
// DBTransformerLayer — staged-GEMM formulation.
//   Node precompute: qkv_dst = x_dst @ Wi^T + bi ; kv_src = x_src @ Weff^T + beff
//   Edge phase:  attn -> o[E*4,128] -> GEMM(wo) -> LN1(+res) -> GEMM(l1,relu)
//                -> GEMM(l2) -> LN2(+res) -> scatter-add ; counts ; divide
// ============================================================================

#define MAX_N 20000
#define MAX_E 100000

// ------------------------------- scratch -----------------------------------
__device__ float g_qkv_dst0[(size_t)MAX_N * 4 * 384];
__device__ float g_qkv_dst1[(size_t)MAX_N * 4 * 384];
__device__ float g_kv_src0[(size_t)MAX_N * 4 * 256];
__device__ float g_kv_src1[(size_t)MAX_N * 4 * 256];
__device__ float g_weff[2 * 256 * 128];
__device__ float g_beff[2 * 256];
__device__ int   g_cnt[2 * MAX_N];
__device__ float g_buf1[(size_t)MAX_E * 512];   // o / xln
__device__ float g_buf2[(size_t)MAX_E * 512];   // u / f
__device__ float g_buf3[(size_t)MAX_E * 256];   // h (FF hidden)

// ------------------------------- zero --------------------------------------
__global__ void zero_kernel(float4* out, int n4, int* cnt, int nc) {
    int stride = gridDim.x * blockDim.x;
    for (int i = blockIdx.x * blockDim.x + threadIdx.x; i < n4; i += stride)
        out[i] = make_float4(0.f, 0.f, 0.f, 0.f);
    for (int i = blockIdx.x * blockDim.x + threadIdx.x; i < nc; i += stride) cnt[i] = 0;
}

// ------------------------------- counts ------------------------------------
__global__ void count_kernel(const int* __restrict__ eAB, const int* __restrict__ eBA,
                             int E0, int E1, int* cnt, int NB) {
    int stride = gridDim.x * blockDim.x;
    int total = E0 + E1;
    for (int i = blockIdx.x * blockDim.x + threadIdx.x; i < total; i += stride) {
        if (i < E0) atomicAdd(&cnt[eAB[E0 + i]], 1);
        else        atomicAdd(&cnt[NB + eBA[E1 + (i - E0)]], 1);
    }
}

// ------------------------ Weff = Wi[128:384] @ bw ---------------------------
__global__ void prep_weff(const float* __restrict__ wi, const float* __restrict__ bi,
                          const float* __restrict__ bw, const float* __restrict__ bb,
                          float* __restrict__ weff, float* __restrict__ beff) {
    int n = blockIdx.x, r = blockIdx.y, k = threadIdx.x;
    const float* wrow = wi + ((size_t)r * 384 + 128 + n) * 128;
    const float* bwr  = bw + (size_t)r * 16384;
    float acc = 0.f;
    for (int m = 0; m < 128; ++m) acc += wrow[m] * bwr[m * 128 + k];
    weff[((size_t)r * 256 + n) * 128 + k] = acc;

    __shared__ float red[128];
    red[k] = wrow[k] * bb[r * 128 + k];
    __syncthreads();
    for (int s = 64; s; s >>= 1) { if (k < s) red[k] += red[k + s]; __syncthreads(); }
    if (k == 0) beff[r * 256 + n] = bi[(size_t)r * 384 + 128 + n] + red[0];
}

// ---------------- GEMM: C[M,Nout] = A[M,K] @ W[Nout,K]^T + b ----------------
// tile 128(M) x 64(N), K-chunks of 32, 256 threads, 8x4 per-thread tile.
__global__ __launch_bounds__(256)
void gemm_tile(const float* __restrict__ A, const float* __restrict__ W,
               const float* __restrict__ bias, float* __restrict__ C,
               int M, int Nout, int K, int relu) {
    __shared__ float As[32 * 132];   // As[k][m]
    __shared__ float Ws[32 * 68];    // Ws[k][n]
    const int bm = blockIdx.x * 128, bn = blockIdx.y * 64;
    const int tid = threadIdx.x;
    const int ty = tid >> 4, tx = tid & 15;

    float acc[8][4];
    #pragma unroll
    for (int i = 0; i < 8; ++i)
        #pragma unroll
        for (int j = 0; j < 4; ++j) acc[i][j] = 0.f;

    for (int kc = 0; kc < K; kc += 32) {
        __syncthreads();
        // load A tile 128x32 (1024 float4)
        #pragma unroll
        for (int it = 0; it < 4; ++it) {
            int idx = tid + it * 256;
            int m = idx >> 3, kq = idx & 7;
            int gm = bm + m;
            float4 a = make_float4(0.f, 0.f, 0.f, 0.f);
            if (gm < M) a = *(const float4*)&A[(size_t)gm * K + kc + kq * 4];
            As[(kq * 4 + 0) * 132 + m] = a.x;
            As[(kq * 4 + 1) * 132 + m] = a.y;
            As[(kq * 4 + 2) * 132 + m] = a.z;
            As[(kq * 4 + 3) * 132 + m] = a.w;
        }
        // load W tile 64x32 (512 float4)
        #pragma unroll
        for (int it = 0; it < 2; ++it) {
            int idx = tid + it * 256;
            int n = idx >> 3, kq = idx & 7;
            float4 w = *(const float4*)&W[(size_t)(bn + n) * K + kc + kq * 4];
            Ws[(kq * 4 + 0) * 68 + n] = w.x;
            Ws[(kq * 4 + 1) * 68 + n] = w.y;
            Ws[(kq * 4 + 2) * 68 + n] = w.z;
            Ws[(kq * 4 + 3) * 68 + n] = w.w;
        }
        __syncthreads();

        #pragma unroll
        for (int k = 0; k < 32; ++k) {
            float4 a0 = *(const float4*)&As[k * 132 + ty * 8];
            float4 a1 = *(const float4*)&As[k * 132 + ty * 8 + 4];
            float4 w0 = *(const float4*)&Ws[k * 68 + tx * 4];
            float am[8] = {a0.x, a0.y, a0.z, a0.w, a1.x, a1.y, a1.z, a1.w};
            #pragma unroll
            for (int i = 0; i < 8; ++i) {
                acc[i][0] += am[i] * w0.x;
                acc[i][1] += am[i] * w0.y;
                acc[i][2] += am[i] * w0.z;
                acc[i][3] += am[i] * w0.w;
            }
        }
    }

    float4 b4 = *(const float4*)&bias[bn + tx * 4];
    #pragma unroll
    for (int i = 0; i < 8; ++i) {
        int gm = bm + ty * 8 + i;
        if (gm < M) {
            float4 o;
            o.x = acc[i][0] + b4.x; o.y = acc[i][1] + b4.y;
            o.z = acc[i][2] + b4.z; o.w = acc[i][3] + b4.w;
            if (relu) {
                o.x = fmaxf(o.x, 0.f); o.y = fmaxf(o.y, 0.f);
                o.z = fmaxf(o.z, 0.f); o.w = fmaxf(o.w, 0.f);
            }
            *(float4*)&C[(size_t)gm * Nout + bn + tx * 4] = o;
        }
    }
}

// ------------------------------- attention ----------------------------------
// per edge: scores(4q x 8kv x 8h, dh=16), softmax, o[4,128] -> obuf
// 2 edges per 256-thread block iteration.
#define A_QD 0
#define A_KV 1536
#define A_SC 2560
#define A_SZ 2816
__global__ __launch_bounds__(256)
void attn_kernel(const int* __restrict__ edge, int E,
                 const float* __restrict__ qkvd, const float* __restrict__ kvs,
                 float* __restrict__ obuf) {
    __shared__ float sm[2 * A_SZ];
    const int tid = threadIdx.x;
    const int h = tid >> 7, lt = tid & 127;
    float* S = sm + h * A_SZ;

    int npair = (E + 1) >> 1;
    for (int p = blockIdx.x; p < npair; p += gridDim.x) {
        __syncthreads();                       // prior iter done with smem
        int e = p * 2 + h;
        bool act = (e < E);
        if (act) {
            int src = edge[e], dst = edge[E + e];
            const float4* pq = (const float4*)(qkvd + (size_t)dst * 1536);
            const float4* pk = (const float4*)(kvs + (size_t)src * 1024);
            *(float4*)&S[A_QD + lt * 4]        = pq[lt];
            *(float4*)&S[A_QD + 512 + lt * 4]  = pq[128 + lt];
            *(float4*)&S[A_QD + 1024 + lt * 4] = pq[256 + lt];
            *(float4*)&S[A_KV + lt * 4]        = pk[lt];
            *(float4*)&S[A_KV + 512 + lt * 4]  = pk[128 + lt];
        }
        __syncthreads();
        if (act) {
            // scores: 2 per thread
            #pragma unroll
            for (int j = 0; j < 2; ++j) {
                int idx = lt * 2 + j;
                int t = idx >> 6, rem = idx & 63, s = rem >> 3, hd = rem & 7;
                const float* qp = &S[A_QD + t * 384 + hd * 16];
                const float* kp = (s < 4) ? &S[A_QD + s * 384 + 128 + hd * 16]
                                          : &S[A_KV + (s - 4) * 256 + hd * 16];
                float acc = 0.f;
                #pragma unroll
                for (int q = 0; q < 16; ++q) acc += qp[q] * kp[q];
                S[A_SC + idx] = acc * 0.25f;
            }
        }
        __syncthreads();
        if (act && lt < 32) {
            int t = lt >> 3, hd = lt & 7;
            float v[8]; float mx = -1e30f;
            #pragma unroll
            for (int s = 0; s < 8; ++s) { v[s] = S[A_SC + t * 64 + s * 8 + hd]; mx = fmaxf(mx, v[s]); }
            float sum = 0.f;
            #pragma unroll
            for (int s = 0; s < 8; ++s) { v[s] = expf(v[s] - mx); sum += v[s]; }
            float inv = 1.f / sum;
            #pragma unroll
            for (int s = 0; s < 8; ++s) S[A_SC + t * 64 + s * 8 + hd] = v[s] * inv;
        }
        __syncthreads();
        if (act) {
            int d = lt, hd = d >> 4;
            #pragma unroll
            for (int t = 0; t < 4; ++t) {
                float acc = 0.f;
                #pragma unroll
                for (int s = 0; s < 8; ++s) {
                    float pp = S[A_SC + t * 64 + s * 8 + hd];
                    float vv = (s < 4) ? S[A_QD + s * 384 + 256 + d]
                                       : S[A_KV + (s - 4) * 256 + 128 + d];
                    acc += pp * vv;
                }
                obuf[((size_t)e * 4 + t) * 128 + d] = acc;
            }
        }
    }
}

// --------------------- LN1: xln = LN(u + x_dst[dst,t]) ----------------------
__global__ void ln_res_kernel(const float* __restrict__ u, const float* __restrict__ xdst,
                              const int* __restrict__ edge, int E,
                              const float* __restrict__ w, const float* __restrict__ b,
                              float* __restrict__ xln) {
    int nwarp = (gridDim.x * blockDim.x) >> 5;
    int wid = (blockIdx.x * blockDim.x + threadIdx.x) >> 5;
    int lane = threadIdx.x & 31;
    int R = E * 4;
    const float4* wp = (const float4*)w;
    const float4* bp = (const float4*)b;
    for (int r = wid; r < R; r += nwarp) {
        int e = r >> 2, t = r & 3;
        int dst = edge[E + e];
        float4 a = ((const float4*)u)[(size_t)r * 32 + lane];
        float4 x = ((const float4*)xdst)[((size_t)dst * 4 + t) * 32 + lane];
        float v0 = a.x + x.x, v1 = a.y + x.y, v2 = a.z + x.z, v3 = a.w + x.w;
        float s1 = v0 + v1 + v2 + v3;
        float s2 = v0 * v0 + v1 * v1 + v2 * v2 + v3 * v3;
        #pragma unroll
        for (int o = 16; o; o >>= 1) {
            s1 += __shfl_xor_sync(0xffffffffu, s1, o);
            s2 += __shfl_xor_sync(0xffffffffu, s2, o);
        }
        float m = s1 * (1.f / 128.f);
        float rs = rsqrtf(s2 * (1.f / 128.f) - m * m + 1e-5f);
        float4 wv = wp[lane], bv = bp[lane];
        float4 o4;
        o4.x = (v0 - m) * rs * wv.x + bv.x;
        o4.y = (v1 - m) * rs * wv.y + bv.y;
        o4.z = (v2 - m) * rs * wv.z + bv.z;
        o4.w = (v3 - m) * rs * wv.w + bv.w;
        ((float4*)xln)[(size_t)r * 32 + lane] = o4;
    }
}

// -------------- LN2 + scatter: out[dst] += LN(f + xln) ----------------------
__global__ void ln2_scatter_kernel(const float* __restrict__ f, const float* __restrict__ xln,
                                   const int* __restrict__ edge, int E,
                                   const float* __restrict__ w, const float* __restrict__ b,
                                   float* __restrict__ out) {
    int nwarp = (gridDim.x * blockDim.x) >> 5;
    int wid = (blockIdx.x * blockDim.x + threadIdx.x) >> 5;
    int lane = threadIdx.x & 31;
    int R = E * 4;
    const float4* wp = (const float4*)w;
    const float4* bp = (const float4*)b;
    for (int r = wid; r < R; r += nwarp) {
        int e = r >> 2, t = r & 3;
        int dst = edge[E + e];
        float4 a = ((const float4*)f)[(size_t)r * 32 + lane];
        float4 x = ((const float4*)xln)[(size_t)r * 32 + lane];
        float v0 = a.x + x.x, v1 = a.y + x.y, v2 = a.z + x.z, v3 = a.w + x.w;
        float s1 = v0 + v1 + v2 + v3;
        float s2 = v0 * v0 + v1 * v1 + v2 * v2 + v3 * v3;
        #pragma unroll
        for (int o = 16; o; o >>= 1) {
            s1 += __shfl_xor_sync(0xffffffffu, s1, o);
            s2 += __shfl_xor_sync(0xffffffffu, s2, o);
        }
        float m = s1 * (1.f / 128.f);
        float rs = rsqrtf(s2 * (1.f / 128.f) - m * m + 1e-5f);
        float4 wv = wp[lane], bv = bp[lane];
        float* ob = out + ((size_t)dst * 4 + t) * 128 + lane * 4;
        atomicAdd(&ob[0], (v0 - m) * rs * wv.x + bv.x);
        atomicAdd(&ob[1], (v1 - m) * rs * wv.y + bv.y);
        atomicAdd(&ob[2], (v2 - m) * rs * wv.z + bv.z);
        atomicAdd(&ob[3], (v3 - m) * rs * wv.w + bv.w);
    }
}

// ------------------------------- finalize -----------------------------------
__global__ void fin_kernel(float* out, const int* cnt, int NA, int NB) {
    int stride = gridDim.x * blockDim.x;
    int nA = NA * 512;
    int total = (NA + NB) * 512;
    for (int i = blockIdx.x * blockDim.x + threadIdx.x; i < total; i += stride) {
        int c;
        if (i < nA) c = cnt[NB + (i >> 9)];
        else        c = cnt[(i - nA) >> 9];
        if (c < 1) c = 1;
        out[i] = out[i] / (float)c;
    }
}

// ------------------------------- launch --------------------------------------
extern "C" void kernel_launch(void* const* d_in, const int* in_sizes, int n_in,
                              void* d_out, int out_size)
{
    const float* x_A = (const float*)d_in[0];
    const float* x_B = (const float*)d_in[1];
    const int*   eAB = (const int*)d_in[2];
    const int*   eBA = (const int*)d_in[3];
    const float* bw  = (const float*)d_in[4];
    const float* bb  = (const float*)d_in[5];
    const float* wi  = (const float*)d_in[6];
    const float* bi  = (const float*)d_in[7];
    const float* wo  = (const float*)d_in[8];
    const float* bo  = (const float*)d_in[9];
    const float* l1w = (const float*)d_in[10];
    const float* l1b = (const float*)d_in[11];
    const float* l2w = (const float*)d_in[12];
    const float* l2b = (const float*)d_in[13];
    const float* n1w = (const float*)d_in[14];
    const float* n1b = (const float*)d_in[15];
    const float* n2w = (const float*)d_in[16];
    const float* n2b = (const float*)d_in[17];
    float* out = (float*)d_out;

    int NA = in_sizes[0] / 512;
    int NB = in_sizes[1] / 512;
    int E0 = in_sizes[2] / 2;
    int E1 = in_sizes[3] / 2;

    float *qd0, *qd1, *kv0, *kv1, *weff, *beff, *b1, *b2, *b3;
    int* cnt;
    cudaGetSymbolAddress((void**)&qd0, g_qkv_dst0);
    cudaGetSymbolAddress((void**)&qd1, g_qkv_dst1);
    cudaGetSymbolAddress((void**)&kv0, g_kv_src0);
    cudaGetSymbolAddress((void**)&kv1, g_kv_src1);
    cudaGetSymbolAddress((void**)&weff, g_weff);
    cudaGetSymbolAddress((void**)&beff, g_beff);
    cudaGetSymbolAddress((void**)&cnt, g_cnt);
    cudaGetSymbolAddress((void**)&b1, g_buf1);
    cudaGetSymbolAddress((void**)&b2, g_buf2);
    cudaGetSymbolAddress((void**)&b3, g_buf3);

    zero_kernel<<<512, 256>>>((float4*)out, (NA + NB) * 128, cnt, NA + NB);
    prep_weff<<<dim3(256, 2), 128>>>(wi, bi, bw, bb, weff, beff);
    count_kernel<<<256, 256>>>(eAB, eBA, E0, E1, cnt, NB);

    // node precompute GEMMs
    gemm_tile<<<dim3((NB * 4 + 127) / 128, 6), 256>>>(x_B, wi,               bi,         qd0, NB * 4, 384, 128, 0);
    gemm_tile<<<dim3((NA * 4 + 127) / 128, 4), 256>>>(x_A, weff,             beff,       kv0, NA * 4, 256, 128, 0);
    gemm_tile<<<dim3((NA * 4 + 127) / 128, 6), 256>>>(x_A, wi + 384 * 128,   bi + 384,   qd1, NA * 4, 384, 128, 0);
    gemm_tile<<<dim3((NB * 4 + 127) / 128, 4), 256>>>(x_B, weff + 256 * 128, beff + 256, kv1, NB * 4, 256, 128, 0);

    // ---- relation 0: A->B updates B ----
    {
        int E = E0, M = E0 * 4;
        float* outB = out + (size_t)NA * 512;
        attn_kernel<<<2048, 256>>>(eAB, E, qd0, kv0, b1);
        gemm_tile<<<dim3((M + 127) / 128, 2), 256>>>(b1, wo, bo, b2, M, 128, 128, 0);
        ln_res_kernel<<<2048, 256>>>(b2, x_B, eAB, E, n1w, n1b, b1);
        gemm_tile<<<dim3((M + 127) / 128, 1), 256>>>(b1, l1w, l1b, b3, M, 64, 128, 1);
        gemm_tile<<<dim3((M + 127) / 128, 2), 256>>>(b3, l2w, l2b, b2, M, 128, 64, 0);
        ln2_scatter_kernel<<<2048, 256>>>(b2, b1, eAB, E, n2w, n2b, outB);
    }
    // ---- relation 1: B->A updates A ----
    {
        int E = E1, M = E1 * 4;
        attn_kernel<<<2048, 256>>>(eBA, E, qd1, kv1, b1);
        gemm_tile<<<dim3((M + 127) / 128, 2), 256>>>(b1, wo + 16384, bo + 128, b2, M, 128, 128, 0);
        ln_res_kernel<<<2048, 256>>>(b2, x_A, eBA, E, n1w + 128, n1b + 128, b1);
        gemm_tile<<<dim3((M + 127) / 128, 1), 256>>>(b1, l1w + 8192, l1b + 64, b3, M, 64, 128, 1);
        gemm_tile<<<dim3((M + 127) / 128, 2), 256>>>(b3, l2w + 8192, l2b + 128, b2, M, 128, 64, 0);
        ln2_scatter_kernel<<<2048, 256>>>(b2, b1, eBA, E, n2w + 128, n2b + 128, out);
    }

    fin_kernel<<<512, 256>>>(out, cnt, NA, NB);
}